// round 13
// baseline (speedup 1.0000x reference)
#include <cuda_runtime.h>
#include <cuda.h>
#include <cuda_fp16.h>
#include <math_constants.h>
#include <cstdint>

// Problem constants (OnlineTripletLoss: B=8192, D=512)
#define BDIM 8192
#define DDIM 512

// GEMM tiling (fp16 mma.sync; tcgen05 is unusable on the compute_103 target)
#define BM 128
#define BN 128
#define BKH 64                       // halves per k-tile = 128 bytes/row (SW128 atom)
#define KTILES (DDIM / BKH)          // 8
#define TILEB (128 * 128)            // one operand tile: 128 rows x 128 bytes = 16 KB
#define STAGEB (2 * TILEB)           // A + P = 32 KB
#define NSTAGE 3
#define SMEMB (NSTAGE * STAGEB)      // 96 KB -> 2 CTAs/SM

// Scratch (device globals: allocation-free per harness rules)
__device__ __align__(16) __half g_A[BDIM * DDIM];
__device__ __align__(16) __half g_P[BDIM * DDIM];
__device__ float g_diag[BDIM];
__device__ unsigned int g_minenc[BDIM];

// ---------------------------------------------------------------------------
// helpers
// ---------------------------------------------------------------------------
__device__ __forceinline__ uint32_t smem_u32(const void* p) {
    uint32_t a;
    asm("{ .reg .u64 t; cvta.to.shared.u64 t, %1; cvt.u32.u64 %0, t; }" : "=r"(a) : "l"(p));
    return a;
}

__device__ __forceinline__ uint32_t sw128(uint32_t off) {
    return off ^ ((off >> 3) & 0x70);
}

__device__ __forceinline__ void ldsm_x4(uint32_t* r, uint32_t addr) {
    asm volatile("ldmatrix.sync.aligned.m8n8.x4.shared.b16 {%0,%1,%2,%3}, [%4];"
                 : "=r"(r[0]), "=r"(r[1]), "=r"(r[2]), "=r"(r[3]) : "r"(addr));
}

// fp16-accumulate HMMA: D(f16x2 pair) = A*B + C(f16x2 pair)
__device__ __forceinline__ void mma16816h(uint32_t* c, const uint32_t* a,
                                          uint32_t b0, uint32_t b1) {
    asm volatile(
        "mma.sync.aligned.m16n8k16.row.col.f16.f16.f16.f16 "
        "{%0,%1}, {%2,%3,%4,%5}, {%6,%7}, {%0,%1};"
        : "+r"(c[0]), "+r"(c[1])
        : "r"(a[0]), "r"(a[1]), "r"(a[2]), "r"(a[3]), "r"(b0), "r"(b1));
}

__device__ __forceinline__ void mbar_init(uint32_t mbar, uint32_t cnt) {
    asm volatile("mbarrier.init.shared.b64 [%0], %1;" :: "r"(mbar), "r"(cnt) : "memory");
}

__device__ __forceinline__ void mbar_expect_tx(uint32_t mbar, uint32_t bytes) {
    asm volatile("mbarrier.arrive.expect_tx.shared.b64 _, [%0], %1;"
                 :: "r"(mbar), "r"(bytes) : "memory");
}

__device__ __forceinline__ void mbar_wait_parity(uint32_t mbar, uint32_t parity) {
    asm volatile(
        "{\n\t.reg .pred P1;\n\t"
        "WAIT_LOOP_%=:\n\t"
        "mbarrier.try_wait.parity.acquire.cta.shared::cta.b64 P1, [%0], %1, 0x989680;\n\t"
        "@P1 bra.uni WAIT_DONE_%=;\n\t"
        "bra.uni WAIT_LOOP_%=;\n\t"
        "WAIT_DONE_%=:\n\t}"
        :: "r"(mbar), "r"(parity) : "memory");
}

__device__ __forceinline__ void tma_load_2d(uint32_t dst, const CUtensorMap* tm,
                                            int x, int y, uint32_t mbar) {
    asm volatile(
        "cp.async.bulk.tensor.2d.shared::cta.global.tile.mbarrier::complete_tx::bytes "
        "[%0], [%1, {%2, %3}], [%4];"
        :: "r"(dst), "l"(tm), "r"(x), "r"(y), "r"(mbar) : "memory");
}

// monotonic unsigned encoding of float for atomicMin
__device__ __forceinline__ unsigned int enc_f32(float v) {
    unsigned int b = __float_as_uint(v);
    return (b & 0x80000000u) ? ~b : (b ^ 0x80000000u);
}
__device__ __forceinline__ float dec_f32(unsigned int e) {
    unsigned int b = (e & 0x80000000u) ? (e ^ 0x80000000u) : ~e;
    return __uint_as_float(b);
}

// ---------------------------------------------------------------------------
// Kernel 1: row-normalize -> fp16, diag cosine (exact fp32), min-enc init.
// Warp-per-row, 4 warps/block. No smem, no __syncthreads.
// ---------------------------------------------------------------------------
__global__ __launch_bounds__(128, 12)
void normalize_diag_kernel(const float* __restrict__ A,
                           const float* __restrict__ P) {
    const int warp = threadIdx.x >> 5;
    const int lane = threadIdx.x & 31;
    const int row = blockIdx.x * 4 + warp;

    const float4* a4 = (const float4*)(A + (size_t)row * DDIM);
    const float4* p4 = (const float4*)(P + (size_t)row * DDIM);

    float4 av[4], pv[4];
    float sa = 0.f, sp = 0.f, sap = 0.f;
    #pragma unroll
    for (int r = 0; r < 4; r++) {
        av[r] = a4[lane + 32 * r];
        pv[r] = p4[lane + 32 * r];
    }
    #pragma unroll
    for (int r = 0; r < 4; r++) {
        sa  += av[r].x * av[r].x + av[r].y * av[r].y + av[r].z * av[r].z + av[r].w * av[r].w;
        sp  += pv[r].x * pv[r].x + pv[r].y * pv[r].y + pv[r].z * pv[r].z + pv[r].w * pv[r].w;
        sap += av[r].x * pv[r].x + av[r].y * pv[r].y + av[r].z * pv[r].z + av[r].w * pv[r].w;
    }
    #pragma unroll
    for (int off = 16; off >= 1; off >>= 1) {
        sa  += __shfl_xor_sync(0xffffffff, sa, off);
        sp  += __shfl_xor_sync(0xffffffff, sp, off);
        sap += __shfl_xor_sync(0xffffffff, sap, off);
    }

    const float inva = rsqrtf(sa);
    const float invp = rsqrtf(sp);

    uint2* ga = (uint2*)(g_A + (size_t)row * DDIM);
    uint2* gp = (uint2*)(g_P + (size_t)row * DDIM);
    #pragma unroll
    for (int r = 0; r < 4; r++) {
        __half2 h0 = __floats2half2_rn(av[r].x * inva, av[r].y * inva);
        __half2 h1 = __floats2half2_rn(av[r].z * inva, av[r].w * inva);
        uint2 u; u.x = *(uint32_t*)&h0; u.y = *(uint32_t*)&h1;
        ga[lane + 32 * r] = u;
        __half2 q0 = __floats2half2_rn(pv[r].x * invp, pv[r].y * invp);
        __half2 q1 = __floats2half2_rn(pv[r].z * invp, pv[r].w * invp);
        uint2 v; v.x = *(uint32_t*)&q0; v.y = *(uint32_t*)&q1;
        gp[lane + 32 * r] = v;
    }

    if (lane == 0) {
        g_diag[row] = sap * inva * invp;
        g_minenc[row] = 0xFFFFFFFFu;
    }
}

// ---------------------------------------------------------------------------
// Kernel 2: fp16 mma.sync fused GEMM + diagonal-masked row-min.
// grid (64, 64): one 128x128 sim tile per CTA. 8 warps (2x4), warp tile 64x32.
// fp16 accumulators within each k-tile (k=64), promoted to fp32 per stage.
// TMA producer, 3-stage mbarrier ring.
// ---------------------------------------------------------------------------
__global__ __launch_bounds__(256, 2)
void gemm_min_mma(const __grid_constant__ CUtensorMap tmA,
                  const __grid_constant__ CUtensorMap tmP) {
    extern __shared__ __align__(1024) char dyn[];
    __shared__ __align__(8) uint64_t s_mbar[NSTAGE];

    const int tid = threadIdx.x;
    const int warp = tid >> 5;
    const int lane = tid & 31;
    const int wm = warp & 1;           // 2 warp-rows of 64
    const int wn = warp >> 1;          // 4 warp-cols of 32
    const int iBase = blockIdx.y * BM;
    const int jBase = blockIdx.x * BN;

    const uint32_t smem = smem_u32(dyn);
    uint32_t mb[NSTAGE];
    #pragma unroll
    for (int s = 0; s < NSTAGE; s++) mb[s] = smem_u32(&s_mbar[s]);

    if (tid == 0) {
        #pragma unroll
        for (int s = 0; s < NSTAGE; s++) mbar_init(mb[s], 1);
    }
    __syncthreads();

    float acc[4][4][4];
    #pragma unroll
    for (int mi = 0; mi < 4; mi++)
        #pragma unroll
        for (int ni = 0; ni < 4; ni++)
            #pragma unroll
            for (int q = 0; q < 4; q++)
                acc[mi][ni][q] = 0.f;

    // producer: single thread issues 2 TMA tile loads per stage
    auto load_stage = [&](int buf, int kt) {
        const uint32_t sbase = smem + buf * STAGEB;
        mbar_expect_tx(mb[buf], STAGEB);
        tma_load_2d(sbase,         &tmA, kt * BKH, iBase, mb[buf]);
        tma_load_2d(sbase + TILEB, &tmP, kt * BKH, jBase, mb[buf]);
    };

    const int lrow = lane & 15;          // ldmatrix source row within 16
    const int lcol = (lane >> 4) * 16;   // 0 or 16 bytes (k halves 0-7 / 8-15)

    auto compute_stage = [&](int buf) {
        const uint32_t aBase = smem + buf * STAGEB;
        const uint32_t pBase = aBase + TILEB;

        // fp16 accumulators for this k-tile (k=64): 2 regs per 16x8 tile
        uint32_t hacc[4][4][2];
        #pragma unroll
        for (int mi = 0; mi < 4; mi++)
            #pragma unroll
            for (int ni = 0; ni < 4; ni++) {
                hacc[mi][ni][0] = 0u;
                hacc[mi][ni][1] = 0u;
            }

        #pragma unroll
        for (int ks = 0; ks < 4; ks++) {
            uint32_t bf[2][4];
            #pragma unroll
            for (int nh = 0; nh < 2; nh++) {
                const int row = wn * 32 + nh * 16 + lrow;
                ldsm_x4(bf[nh], pBase + sw128(row * 128 + ks * 32 + lcol));
            }
            // process M in pairs to cap fragment register liveness
            #pragma unroll
            for (int mp = 0; mp < 2; mp++) {
                uint32_t af[2][4];
                #pragma unroll
                for (int i = 0; i < 2; i++) {
                    const int row = wm * 64 + (mp * 2 + i) * 16 + lrow;
                    ldsm_x4(af[i], aBase + sw128(row * 128 + ks * 32 + lcol));
                }
                #pragma unroll
                for (int i = 0; i < 2; i++) {
                    #pragma unroll
                    for (int ni = 0; ni < 4; ni++) {
                        const int nh = ni >> 1, sel = ni & 1;
                        mma16816h(hacc[mp * 2 + i][ni], af[i],
                                  bf[nh][sel], bf[nh][sel + 2]);
                    }
                }
            }
        }

        // promote this k-tile's fp16 partial sums into the fp32 accumulators
        #pragma unroll
        for (int mi = 0; mi < 4; mi++)
            #pragma unroll
            for (int ni = 0; ni < 4; ni++) {
                const float2 lo = __half22float2(*(__half2*)&hacc[mi][ni][0]);
                const float2 hi = __half22float2(*(__half2*)&hacc[mi][ni][1]);
                acc[mi][ni][0] += lo.x;
                acc[mi][ni][1] += lo.y;
                acc[mi][ni][2] += hi.x;
                acc[mi][ni][3] += hi.y;
            }
    };

    // 3-stage ring, lookahead 2
    if (tid == 0) {
        load_stage(0, 0);
        load_stage(1, 1);
    }
    for (int kt = 0; kt < KTILES; kt++) {
        if (kt + 2 < KTILES && tid == 0)
            load_stage((kt + 2) % NSTAGE, kt + 2);
        mbar_wait_parity(mb[kt % NSTAGE], (uint32_t)((kt / NSTAGE) & 1));
        compute_stage(kt % NSTAGE);
        __syncthreads();
    }

    // epilogue: diagonal-masked row-min, lane-quad reduce, global atomicMin
    #pragma unroll
    for (int mi = 0; mi < 4; mi++) {
        #pragma unroll
        for (int half = 0; half < 2; half++) {
            const int gi = iBase + wm * 64 + mi * 16 + (lane >> 2) + half * 8;
            float vmin = CUDART_INF_F;
            #pragma unroll
            for (int ni = 0; ni < 4; ni++) {
                const int gj0 = jBase + wn * 32 + ni * 8 + 2 * (lane & 3);
                const float v0 = (gi == gj0)     ? CUDART_INF_F : acc[mi][ni][half * 2 + 0];
                const float v1 = (gi == gj0 + 1) ? CUDART_INF_F : acc[mi][ni][half * 2 + 1];
                vmin = fminf(vmin, fminf(v0, v1));
            }
            vmin = fminf(vmin, __shfl_xor_sync(0xffffffff, vmin, 1));
            vmin = fminf(vmin, __shfl_xor_sync(0xffffffff, vmin, 2));
            if ((lane & 3) == 0)
                atomicMin(&g_minenc[gi], enc_f32(vmin));
        }
    }
}

// ---------------------------------------------------------------------------
// Kernel 3: decode per-row min, compute mean relu(1 + diag - min)
// ---------------------------------------------------------------------------
__global__ __launch_bounds__(1024)
void final_loss_kernel(float* __restrict__ out) {
    const int t = threadIdx.x;   // 1024
    float sum = 0.f;
    for (int i = t; i < BDIM; i += 1024) {
        const float m = dec_f32(g_minenc[i]);
        const float l = 1.0f + g_diag[i] - m;
        sum += (l > 0.f) ? l : 0.f;
    }
    #pragma unroll
    for (int off = 16; off >= 1; off >>= 1)
        sum += __shfl_xor_sync(0xffffffff, sum, off);
    __shared__ float red[32];
    const int warp = t >> 5, lane = t & 31;
    if (lane == 0) red[warp] = sum;
    __syncthreads();
    if (warp == 0) {
        float v = red[lane];
        #pragma unroll
        for (int off = 16; off >= 1; off >>= 1)
            v += __shfl_xor_sync(0xffffffff, v, off);
        if (lane == 0) out[0] = v / (float)BDIM;
    }
}

// ---------------------------------------------------------------------------
// host-side tensormap encoding (runtime-resolved driver entry point; no -lcuda)
// ---------------------------------------------------------------------------
typedef CUresult (*EncodeTiledFn)(
    CUtensorMap*, CUtensorMapDataType, cuuint32_t, void*,
    const cuuint64_t*, const cuuint64_t*, const cuuint32_t*, const cuuint32_t*,
    CUtensorMapInterleave, CUtensorMapSwizzle, CUtensorMapL2promotion,
    CUtensorMapFloatOOBfill);

static void encode_map(EncodeTiledFn enc, CUtensorMap* tm, void* base) {
    cuuint64_t dims[2]    = { (cuuint64_t)DDIM, (cuuint64_t)BDIM };
    cuuint64_t strides[1] = { (cuuint64_t)DDIM * sizeof(__half) };
    cuuint32_t box[2]     = { (cuuint32_t)BKH, (cuuint32_t)BM };   // 128 B x 128 rows
    cuuint32_t estr[2]    = { 1, 1 };
    enc(tm, CU_TENSOR_MAP_DATA_TYPE_FLOAT16, 2, base,
        dims, strides, box, estr,
        CU_TENSOR_MAP_INTERLEAVE_NONE, CU_TENSOR_MAP_SWIZZLE_128B,
        CU_TENSOR_MAP_L2_PROMOTION_L2_128B, CU_TENSOR_MAP_FLOAT_OOB_FILL_NONE);
}

extern "C" void kernel_launch(void* const* d_in, const int* in_sizes, int n_in,
                              void* d_out, int out_size) {
    const float* anchor   = (const float*)d_in[0];
    const float* positive = (const float*)d_in[1];
    float* out = (float*)d_out;

    // resolve cuTensorMapEncodeTiled through cudart (host-only, graph-safe)
    EncodeTiledFn enc = nullptr;
    cudaDriverEntryPointQueryResult qres;
    cudaGetDriverEntryPoint("cuTensorMapEncodeTiled", (void**)&enc,
                            cudaEnableDefault, &qres);

    void *pa = nullptr, *pp = nullptr;
    cudaGetSymbolAddress(&pa, g_A);
    cudaGetSymbolAddress(&pp, g_P);

    CUtensorMap tmA, tmP;
    encode_map(enc, &tmA, pa);
    encode_map(enc, &tmP, pp);

    cudaFuncSetAttribute(gemm_min_mma, cudaFuncAttributeMaxDynamicSharedMemorySize, SMEMB);

    normalize_diag_kernel<<<BDIM / 4, 128>>>(anchor, positive);
    dim3 grid(BDIM / BN, BDIM / BM);
    gemm_min_mma<<<grid, 256, SMEMB>>>(tmA, tmP);
    final_loss_kernel<<<1, 1024>>>(out);
}

// round 14
// speedup vs baseline: 1.1590x; 1.1590x over previous
#include <cuda_runtime.h>
#include <cuda.h>
#include <cuda_fp16.h>
#include <math_constants.h>
#include <cstdint>

// Problem constants (OnlineTripletLoss: B=8192, D=512)
#define BDIM 8192
#define DDIM 512

// GEMM tiling (fp16 mma.sync; tcgen05 is unusable on the compute_103 target)
#define BM 128
#define BN 128
#define BKH 64                       // halves per k-tile = 128 bytes/row (SW128 atom)
#define KTILES (DDIM / BKH)          // 8
#define TILEB (128 * 128)            // one operand tile: 128 rows x 128 bytes = 16 KB
#define STAGEB (2 * TILEB)           // A + P = 32 KB
#define NSTAGE 3
#define SMEMB (NSTAGE * STAGEB)      // 96 KB -> 2 CTAs/SM
#define NTILES ((BDIM / BM) * (BDIM / BN))   // 4096 CTAs

// Scratch (device globals: allocation-free per harness rules)
__device__ __align__(16) __half g_A[BDIM * DDIM];
__device__ __align__(16) __half g_P[BDIM * DDIM];
__device__ float g_diag[BDIM];
__device__ unsigned int g_minenc[BDIM];
__device__ int g_ticket = 0;          // returns to 0 every call (last CTA resets)

// ---------------------------------------------------------------------------
// helpers
// ---------------------------------------------------------------------------
__device__ __forceinline__ uint32_t smem_u32(const void* p) {
    uint32_t a;
    asm("{ .reg .u64 t; cvta.to.shared.u64 t, %1; cvt.u32.u64 %0, t; }" : "=r"(a) : "l"(p));
    return a;
}

__device__ __forceinline__ uint32_t sw128(uint32_t off) {
    return off ^ ((off >> 3) & 0x70);
}

__device__ __forceinline__ void ldsm_x4(uint32_t* r, uint32_t addr) {
    asm volatile("ldmatrix.sync.aligned.m8n8.x4.shared.b16 {%0,%1,%2,%3}, [%4];"
                 : "=r"(r[0]), "=r"(r[1]), "=r"(r[2]), "=r"(r[3]) : "r"(addr));
}

__device__ __forceinline__ void mma16816(float* c, const uint32_t* a,
                                         uint32_t b0, uint32_t b1) {
    asm volatile(
        "mma.sync.aligned.m16n8k16.row.col.f32.f16.f16.f32 "
        "{%0,%1,%2,%3}, {%4,%5,%6,%7}, {%8,%9}, {%0,%1,%2,%3};"
        : "+f"(c[0]), "+f"(c[1]), "+f"(c[2]), "+f"(c[3])
        : "r"(a[0]), "r"(a[1]), "r"(a[2]), "r"(a[3]), "r"(b0), "r"(b1));
}

__device__ __forceinline__ void mbar_init(uint32_t mbar, uint32_t cnt) {
    asm volatile("mbarrier.init.shared.b64 [%0], %1;" :: "r"(mbar), "r"(cnt) : "memory");
}

__device__ __forceinline__ void mbar_expect_tx(uint32_t mbar, uint32_t bytes) {
    asm volatile("mbarrier.arrive.expect_tx.shared.b64 _, [%0], %1;"
                 :: "r"(mbar), "r"(bytes) : "memory");
}

__device__ __forceinline__ void mbar_wait_parity(uint32_t mbar, uint32_t parity) {
    asm volatile(
        "{\n\t.reg .pred P1;\n\t"
        "WAIT_LOOP_%=:\n\t"
        "mbarrier.try_wait.parity.acquire.cta.shared::cta.b64 P1, [%0], %1, 0x989680;\n\t"
        "@P1 bra.uni WAIT_DONE_%=;\n\t"
        "bra.uni WAIT_LOOP_%=;\n\t"
        "WAIT_DONE_%=:\n\t}"
        :: "r"(mbar), "r"(parity) : "memory");
}

__device__ __forceinline__ void tma_load_2d(uint32_t dst, const CUtensorMap* tm,
                                            int x, int y, uint32_t mbar) {
    asm volatile(
        "cp.async.bulk.tensor.2d.shared::cta.global.tile.mbarrier::complete_tx::bytes "
        "[%0], [%1, {%2, %3}], [%4];"
        :: "r"(dst), "l"(tm), "r"(x), "r"(y), "r"(mbar) : "memory");
}

// monotonic unsigned encoding of float for atomicMin
__device__ __forceinline__ unsigned int enc_f32(float v) {
    unsigned int b = __float_as_uint(v);
    return (b & 0x80000000u) ? ~b : (b ^ 0x80000000u);
}
__device__ __forceinline__ float dec_f32(unsigned int e) {
    unsigned int b = (e & 0x80000000u) ? (e ^ 0x80000000u) : ~e;
    return __uint_as_float(b);
}

// ---------------------------------------------------------------------------
// Kernel 1: row-normalize -> fp16, diag cosine (exact fp32), min-enc init.
// Warp-per-row, 4 warps/block. No smem, no __syncthreads.
// ---------------------------------------------------------------------------
__global__ __launch_bounds__(128, 12)
void normalize_diag_kernel(const float* __restrict__ A,
                           const float* __restrict__ P) {
    const int warp = threadIdx.x >> 5;
    const int lane = threadIdx.x & 31;
    const int row = blockIdx.x * 4 + warp;

    const float4* a4 = (const float4*)(A + (size_t)row * DDIM);
    const float4* p4 = (const float4*)(P + (size_t)row * DDIM);

    float4 av[4], pv[4];
    float sa = 0.f, sp = 0.f, sap = 0.f;
    #pragma unroll
    for (int r = 0; r < 4; r++) {
        av[r] = a4[lane + 32 * r];
        pv[r] = p4[lane + 32 * r];
    }
    #pragma unroll
    for (int r = 0; r < 4; r++) {
        sa  += av[r].x * av[r].x + av[r].y * av[r].y + av[r].z * av[r].z + av[r].w * av[r].w;
        sp  += pv[r].x * pv[r].x + pv[r].y * pv[r].y + pv[r].z * pv[r].z + pv[r].w * pv[r].w;
        sap += av[r].x * pv[r].x + av[r].y * pv[r].y + av[r].z * pv[r].z + av[r].w * pv[r].w;
    }
    #pragma unroll
    for (int off = 16; off >= 1; off >>= 1) {
        sa  += __shfl_xor_sync(0xffffffff, sa, off);
        sp  += __shfl_xor_sync(0xffffffff, sp, off);
        sap += __shfl_xor_sync(0xffffffff, sap, off);
    }

    const float inva = rsqrtf(sa);
    const float invp = rsqrtf(sp);

    uint2* ga = (uint2*)(g_A + (size_t)row * DDIM);
    uint2* gp = (uint2*)(g_P + (size_t)row * DDIM);
    #pragma unroll
    for (int r = 0; r < 4; r++) {
        __half2 h0 = __floats2half2_rn(av[r].x * inva, av[r].y * inva);
        __half2 h1 = __floats2half2_rn(av[r].z * inva, av[r].w * inva);
        uint2 u; u.x = *(uint32_t*)&h0; u.y = *(uint32_t*)&h1;
        ga[lane + 32 * r] = u;
        __half2 q0 = __floats2half2_rn(pv[r].x * invp, pv[r].y * invp);
        __half2 q1 = __floats2half2_rn(pv[r].z * invp, pv[r].w * invp);
        uint2 v; v.x = *(uint32_t*)&q0; v.y = *(uint32_t*)&q1;
        gp[lane + 32 * r] = v;
    }

    if (lane == 0) {
        g_diag[row] = sap * inva * invp;
        g_minenc[row] = 0xFFFFFFFFu;
    }
}

// ---------------------------------------------------------------------------
// Kernel 2: fp16 mma.sync fused GEMM + diagonal-masked row-min + fused
// final-loss (last-CTA-done). grid (64, 64): one 128x128 sim tile per CTA.
// 8 warps (2x4), warp tile 64x32. TMA producer, 3-stage mbarrier ring.
// ---------------------------------------------------------------------------
__global__ __launch_bounds__(256, 2)
void gemm_min_mma(const __grid_constant__ CUtensorMap tmA,
                  const __grid_constant__ CUtensorMap tmP,
                  float* __restrict__ out) {
    extern __shared__ __align__(1024) char dyn[];
    __shared__ __align__(8) uint64_t s_mbar[NSTAGE];
    __shared__ int s_islast;

    const int tid = threadIdx.x;
    const int warp = tid >> 5;
    const int lane = tid & 31;
    const int wm = warp & 1;           // 2 warp-rows of 64
    const int wn = warp >> 1;          // 4 warp-cols of 32
    const int iBase = blockIdx.y * BM;
    const int jBase = blockIdx.x * BN;

    const uint32_t smem = smem_u32(dyn);
    uint32_t mb[NSTAGE];
    #pragma unroll
    for (int s = 0; s < NSTAGE; s++) mb[s] = smem_u32(&s_mbar[s]);

    if (tid == 0) {
        #pragma unroll
        for (int s = 0; s < NSTAGE; s++) mbar_init(mb[s], 1);
    }
    __syncthreads();

    float acc[4][4][4];
    #pragma unroll
    for (int mi = 0; mi < 4; mi++)
        #pragma unroll
        for (int ni = 0; ni < 4; ni++)
            #pragma unroll
            for (int q = 0; q < 4; q++)
                acc[mi][ni][q] = 0.f;

    // producer: single thread issues 2 TMA tile loads per stage
    auto load_stage = [&](int buf, int kt) {
        const uint32_t sbase = smem + buf * STAGEB;
        mbar_expect_tx(mb[buf], STAGEB);
        tma_load_2d(sbase,         &tmA, kt * BKH, iBase, mb[buf]);
        tma_load_2d(sbase + TILEB, &tmP, kt * BKH, jBase, mb[buf]);
    };

    const int lrow = lane & 15;          // ldmatrix source row within 16
    const int lcol = (lane >> 4) * 16;   // 0 or 16 bytes (k halves 0-7 / 8-15)

    auto compute_stage = [&](int buf) {
        const uint32_t aBase = smem + buf * STAGEB;
        const uint32_t pBase = aBase + TILEB;
        #pragma unroll
        for (int ks = 0; ks < 4; ks++) {
            uint32_t af[4][4];
            #pragma unroll
            for (int mi = 0; mi < 4; mi++) {
                const int row = wm * 64 + mi * 16 + lrow;
                ldsm_x4(af[mi], aBase + sw128(row * 128 + ks * 32 + lcol));
            }
            uint32_t bf[2][4];
            #pragma unroll
            for (int nh = 0; nh < 2; nh++) {
                const int row = wn * 32 + nh * 16 + lrow;
                ldsm_x4(bf[nh], pBase + sw128(row * 128 + ks * 32 + lcol));
            }
            #pragma unroll
            for (int mi = 0; mi < 4; mi++) {
                #pragma unroll
                for (int ni = 0; ni < 4; ni++) {
                    const int nh = ni >> 1, sel = ni & 1;
                    mma16816(acc[mi][ni], af[mi], bf[nh][sel], bf[nh][sel + 2]);
                }
            }
        }
    };

    // 3-stage ring, lookahead 2
    if (tid == 0) {
        load_stage(0, 0);
        load_stage(1, 1);
    }
    for (int kt = 0; kt < KTILES; kt++) {
        if (kt + 2 < KTILES && tid == 0)
            load_stage((kt + 2) % NSTAGE, kt + 2);
        mbar_wait_parity(mb[kt % NSTAGE], (uint32_t)((kt / NSTAGE) & 1));
        compute_stage(kt % NSTAGE);
        __syncthreads();
    }

    // epilogue: diagonal-masked row-min, lane-quad reduce, global atomicMin
    #pragma unroll
    for (int mi = 0; mi < 4; mi++) {
        #pragma unroll
        for (int half = 0; half < 2; half++) {
            const int gi = iBase + wm * 64 + mi * 16 + (lane >> 2) + half * 8;
            float vmin = CUDART_INF_F;
            #pragma unroll
            for (int ni = 0; ni < 4; ni++) {
                const int gj0 = jBase + wn * 32 + ni * 8 + 2 * (lane & 3);
                const float v0 = (gi == gj0)     ? CUDART_INF_F : acc[mi][ni][half * 2 + 0];
                const float v1 = (gi == gj0 + 1) ? CUDART_INF_F : acc[mi][ni][half * 2 + 1];
                vmin = fminf(vmin, fminf(v0, v1));
            }
            vmin = fminf(vmin, __shfl_xor_sync(0xffffffff, vmin, 1));
            vmin = fminf(vmin, __shfl_xor_sync(0xffffffff, vmin, 2));
            if ((lane & 3) == 0)
                atomicMin(&g_minenc[gi], enc_f32(vmin));
        }
    }

    // fused finalization: last CTA to finish computes the loss
    __syncthreads();
    if (tid == 0) {
        __threadfence();                                  // publish atomicMins
        const int ticket = atomicAdd(&g_ticket, 1);
        s_islast = (ticket == NTILES - 1) ? 1 : 0;
    }
    __syncthreads();

    if (s_islast) {
        __threadfence();                                  // acquire all CTAs' mins
        float sum = 0.f;
        for (int i = tid; i < BDIM; i += 256) {
            const float m = dec_f32(g_minenc[i]);
            const float l = 1.0f + g_diag[i] - m;
            sum += (l > 0.f) ? l : 0.f;
        }
        #pragma unroll
        for (int off = 16; off >= 1; off >>= 1)
            sum += __shfl_xor_sync(0xffffffff, sum, off);
        __shared__ float red[8];
        if (lane == 0) red[warp] = sum;
        __syncthreads();
        if (tid == 0) {
            float total = 0.f;
            #pragma unroll
            for (int w = 0; w < 8; w++) total += red[w];
            out[0] = total / (float)BDIM;
            g_ticket = 0;                                 // reset for graph replay
        }
    }
}

// ---------------------------------------------------------------------------
// host-side tensormap encoding (runtime-resolved driver entry point; no -lcuda)
// ---------------------------------------------------------------------------
typedef CUresult (*EncodeTiledFn)(
    CUtensorMap*, CUtensorMapDataType, cuuint32_t, void*,
    const cuuint64_t*, const cuuint64_t*, const cuuint32_t*, const cuuint32_t*,
    CUtensorMapInterleave, CUtensorMapSwizzle, CUtensorMapL2promotion,
    CUtensorMapFloatOOBfill);

static void encode_map(EncodeTiledFn enc, CUtensorMap* tm, void* base) {
    cuuint64_t dims[2]    = { (cuuint64_t)DDIM, (cuuint64_t)BDIM };
    cuuint64_t strides[1] = { (cuuint64_t)DDIM * sizeof(__half) };
    cuuint32_t box[2]     = { (cuuint32_t)BKH, (cuuint32_t)BM };   // 128 B x 128 rows
    cuuint32_t estr[2]    = { 1, 1 };
    enc(tm, CU_TENSOR_MAP_DATA_TYPE_FLOAT16, 2, base,
        dims, strides, box, estr,
        CU_TENSOR_MAP_INTERLEAVE_NONE, CU_TENSOR_MAP_SWIZZLE_128B,
        CU_TENSOR_MAP_L2_PROMOTION_L2_128B, CU_TENSOR_MAP_FLOAT_OOB_FILL_NONE);
}

extern "C" void kernel_launch(void* const* d_in, const int* in_sizes, int n_in,
                              void* d_out, int out_size) {
    const float* anchor   = (const float*)d_in[0];
    const float* positive = (const float*)d_in[1];
    float* out = (float*)d_out;

    // resolve cuTensorMapEncodeTiled through cudart (host-only, graph-safe)
    EncodeTiledFn enc = nullptr;
    cudaDriverEntryPointQueryResult qres;
    cudaGetDriverEntryPoint("cuTensorMapEncodeTiled", (void**)&enc,
                            cudaEnableDefault, &qres);

    void *pa = nullptr, *pp = nullptr;
    cudaGetSymbolAddress(&pa, g_A);
    cudaGetSymbolAddress(&pp, g_P);

    CUtensorMap tmA, tmP;
    encode_map(enc, &tmA, pa);
    encode_map(enc, &tmP, pp);

    cudaFuncSetAttribute(gemm_min_mma, cudaFuncAttributeMaxDynamicSharedMemorySize, SMEMB);

    normalize_diag_kernel<<<BDIM / 4, 128>>>(anchor, positive);
    dim3 grid(BDIM / BN, BDIM / BM);
    gemm_min_mma<<<grid, 256, SMEMB>>>(tmA, tmP, out);
}

// round 15
// speedup vs baseline: 1.2072x; 1.0416x over previous
#include <cuda_runtime.h>
#include <cuda.h>
#include <cuda_fp16.h>
#include <math_constants.h>
#include <cstdint>

// Problem constants (OnlineTripletLoss: B=8192, D=512)
#define BDIM 8192
#define DDIM 512

// GEMM tiling (fp16 mma.sync; tcgen05 is unusable on the compute_103 target)
#define BM 128
#define BN 128
#define BKH 64                       // halves per k-tile = 128 bytes/row (SW128 atom)
#define KTILES (DDIM / BKH)          // 8
#define TILEB (128 * 128)            // one operand tile: 128 rows x 128 bytes = 16 KB
#define STAGEB (2 * TILEB)           // A + P = 32 KB
#define NSTAGE 3
#define SMEMB (NSTAGE * STAGEB)      // 96 KB -> 2 CTAs/SM

// Scratch (device globals: allocation-free per harness rules)
__device__ __align__(16) __half g_A[BDIM * DDIM];
__device__ __align__(16) __half g_P[BDIM * DDIM];
__device__ float g_diag[BDIM];
__device__ unsigned int g_minenc[BDIM];

// ---------------------------------------------------------------------------
// helpers
// ---------------------------------------------------------------------------
__device__ __forceinline__ uint32_t smem_u32(const void* p) {
    uint32_t a;
    asm("{ .reg .u64 t; cvta.to.shared.u64 t, %1; cvt.u32.u64 %0, t; }" : "=r"(a) : "l"(p));
    return a;
}

__device__ __forceinline__ uint32_t sw128(uint32_t off) {
    return off ^ ((off >> 3) & 0x70);
}

__device__ __forceinline__ void ldsm_x4(uint32_t* r, uint32_t addr) {
    asm volatile("ldmatrix.sync.aligned.m8n8.x4.shared.b16 {%0,%1,%2,%3}, [%4];"
                 : "=r"(r[0]), "=r"(r[1]), "=r"(r[2]), "=r"(r[3]) : "r"(addr));
}

__device__ __forceinline__ void mma16816(float* c, const uint32_t* a,
                                         uint32_t b0, uint32_t b1) {
    asm volatile(
        "mma.sync.aligned.m16n8k16.row.col.f32.f16.f16.f32 "
        "{%0,%1,%2,%3}, {%4,%5,%6,%7}, {%8,%9}, {%0,%1,%2,%3};"
        : "+f"(c[0]), "+f"(c[1]), "+f"(c[2]), "+f"(c[3])
        : "r"(a[0]), "r"(a[1]), "r"(a[2]), "r"(a[3]), "r"(b0), "r"(b1));
}

__device__ __forceinline__ void mbar_init(uint32_t mbar, uint32_t cnt) {
    asm volatile("mbarrier.init.shared.b64 [%0], %1;" :: "r"(mbar), "r"(cnt) : "memory");
}

__device__ __forceinline__ void mbar_arrive(uint32_t mbar) {
    asm volatile("mbarrier.arrive.shared.b64 _, [%0];" :: "r"(mbar) : "memory");
}

__device__ __forceinline__ void mbar_expect_tx(uint32_t mbar, uint32_t bytes) {
    asm volatile("mbarrier.arrive.expect_tx.shared.b64 _, [%0], %1;"
                 :: "r"(mbar), "r"(bytes) : "memory");
}

__device__ __forceinline__ void mbar_wait_parity(uint32_t mbar, uint32_t parity) {
    asm volatile(
        "{\n\t.reg .pred P1;\n\t"
        "WAIT_LOOP_%=:\n\t"
        "mbarrier.try_wait.parity.acquire.cta.shared::cta.b64 P1, [%0], %1, 0x989680;\n\t"
        "@P1 bra.uni WAIT_DONE_%=;\n\t"
        "bra.uni WAIT_LOOP_%=;\n\t"
        "WAIT_DONE_%=:\n\t}"
        :: "r"(mbar), "r"(parity) : "memory");
}

__device__ __forceinline__ void tma_load_2d(uint32_t dst, const CUtensorMap* tm,
                                            int x, int y, uint32_t mbar) {
    asm volatile(
        "cp.async.bulk.tensor.2d.shared::cta.global.tile.mbarrier::complete_tx::bytes "
        "[%0], [%1, {%2, %3}], [%4];"
        :: "r"(dst), "l"(tm), "r"(x), "r"(y), "r"(mbar) : "memory");
}

// monotonic unsigned encoding of float for atomicMin
__device__ __forceinline__ unsigned int enc_f32(float v) {
    unsigned int b = __float_as_uint(v);
    return (b & 0x80000000u) ? ~b : (b ^ 0x80000000u);
}
__device__ __forceinline__ float dec_f32(unsigned int e) {
    unsigned int b = (e & 0x80000000u) ? (e ^ 0x80000000u) : ~e;
    return __uint_as_float(b);
}

// ---------------------------------------------------------------------------
// Kernel 1: row-normalize -> fp16, diag cosine (exact fp32), min-enc init.
// Warp-per-row, 4 warps/block. No smem, no __syncthreads.
// ---------------------------------------------------------------------------
__global__ __launch_bounds__(128, 12)
void normalize_diag_kernel(const float* __restrict__ A,
                           const float* __restrict__ P) {
    const int warp = threadIdx.x >> 5;
    const int lane = threadIdx.x & 31;
    const int row = blockIdx.x * 4 + warp;

    const float4* a4 = (const float4*)(A + (size_t)row * DDIM);
    const float4* p4 = (const float4*)(P + (size_t)row * DDIM);

    float4 av[4], pv[4];
    float sa = 0.f, sp = 0.f, sap = 0.f;
    #pragma unroll
    for (int r = 0; r < 4; r++) {
        av[r] = a4[lane + 32 * r];
        pv[r] = p4[lane + 32 * r];
    }
    #pragma unroll
    for (int r = 0; r < 4; r++) {
        sa  += av[r].x * av[r].x + av[r].y * av[r].y + av[r].z * av[r].z + av[r].w * av[r].w;
        sp  += pv[r].x * pv[r].x + pv[r].y * pv[r].y + pv[r].z * pv[r].z + pv[r].w * pv[r].w;
        sap += av[r].x * pv[r].x + av[r].y * pv[r].y + av[r].z * pv[r].z + av[r].w * pv[r].w;
    }
    #pragma unroll
    for (int off = 16; off >= 1; off >>= 1) {
        sa  += __shfl_xor_sync(0xffffffff, sa, off);
        sp  += __shfl_xor_sync(0xffffffff, sp, off);
        sap += __shfl_xor_sync(0xffffffff, sap, off);
    }

    const float inva = rsqrtf(sa);
    const float invp = rsqrtf(sp);

    uint2* ga = (uint2*)(g_A + (size_t)row * DDIM);
    uint2* gp = (uint2*)(g_P + (size_t)row * DDIM);
    #pragma unroll
    for (int r = 0; r < 4; r++) {
        __half2 h0 = __floats2half2_rn(av[r].x * inva, av[r].y * inva);
        __half2 h1 = __floats2half2_rn(av[r].z * inva, av[r].w * inva);
        uint2 u; u.x = *(uint32_t*)&h0; u.y = *(uint32_t*)&h1;
        ga[lane + 32 * r] = u;
        __half2 q0 = __floats2half2_rn(pv[r].x * invp, pv[r].y * invp);
        __half2 q1 = __floats2half2_rn(pv[r].z * invp, pv[r].w * invp);
        uint2 v; v.x = *(uint32_t*)&q0; v.y = *(uint32_t*)&q1;
        gp[lane + 32 * r] = v;
    }

    if (lane == 0) {
        g_diag[row] = sap * inva * invp;
        g_minenc[row] = 0xFFFFFFFFu;
    }
}

// ---------------------------------------------------------------------------
// Kernel 2: fp16 mma.sync fused GEMM + diagonal-masked row-min.
// grid (64, 64): one 128x128 sim tile per CTA. 8 warps (2x4), warp tile 64x32.
// TMA producer with full/empty mbarrier ring — NO in-loop __syncthreads, so
// warps desynchronize and LDSM bursts overlap other warps' HMMA bursts.
// ---------------------------------------------------------------------------
__global__ __launch_bounds__(256, 2)
void gemm_min_mma(const __grid_constant__ CUtensorMap tmA,
                  const __grid_constant__ CUtensorMap tmP) {
    extern __shared__ __align__(1024) char dyn[];
    __shared__ __align__(8) uint64_t s_full[NSTAGE];
    __shared__ __align__(8) uint64_t s_empty[NSTAGE];

    const int tid = threadIdx.x;
    const int warp = tid >> 5;
    const int lane = tid & 31;
    const int wm = warp & 1;           // 2 warp-rows of 64
    const int wn = warp >> 1;          // 4 warp-cols of 32
    const int iBase = blockIdx.y * BM;
    const int jBase = blockIdx.x * BN;

    const uint32_t smem = smem_u32(dyn);
    uint32_t mbF[NSTAGE], mbE[NSTAGE];
    #pragma unroll
    for (int s = 0; s < NSTAGE; s++) {
        mbF[s] = smem_u32(&s_full[s]);
        mbE[s] = smem_u32(&s_empty[s]);
    }

    if (tid == 0) {
        #pragma unroll
        for (int s = 0; s < NSTAGE; s++) {
            mbar_init(mbF[s], 1);      // full: one TMA tx completion
            mbar_init(mbE[s], 8);      // empty: one arrive per warp
        }
    }
    __syncthreads();                    // barriers visible (only CTA-wide sync)

    float acc[4][4][4];
    #pragma unroll
    for (int mi = 0; mi < 4; mi++)
        #pragma unroll
        for (int ni = 0; ni < 4; ni++)
            #pragma unroll
            for (int q = 0; q < 4; q++)
                acc[mi][ni][q] = 0.f;

    // producer: single thread issues 2 TMA tile loads per stage
    auto load_stage = [&](int buf, int kt) {
        const uint32_t sbase = smem + buf * STAGEB;
        mbar_expect_tx(mbF[buf], STAGEB);
        tma_load_2d(sbase,         &tmA, kt * BKH, iBase, mbF[buf]);
        tma_load_2d(sbase + TILEB, &tmP, kt * BKH, jBase, mbF[buf]);
    };

    const int lrow = lane & 15;          // ldmatrix source row within 16
    const int lcol = (lane >> 4) * 16;   // 0 or 16 bytes (k halves 0-7 / 8-15)

    auto compute_stage = [&](int buf) {
        const uint32_t aBase = smem + buf * STAGEB;
        const uint32_t pBase = aBase + TILEB;
        #pragma unroll
        for (int ks = 0; ks < 4; ks++) {
            uint32_t af[4][4];
            #pragma unroll
            for (int mi = 0; mi < 4; mi++) {
                const int row = wm * 64 + mi * 16 + lrow;
                ldsm_x4(af[mi], aBase + sw128(row * 128 + ks * 32 + lcol));
            }
            uint32_t bf[2][4];
            #pragma unroll
            for (int nh = 0; nh < 2; nh++) {
                const int row = wn * 32 + nh * 16 + lrow;
                ldsm_x4(bf[nh], pBase + sw128(row * 128 + ks * 32 + lcol));
            }
            #pragma unroll
            for (int mi = 0; mi < 4; mi++) {
                #pragma unroll
                for (int ni = 0; ni < 4; ni++) {
                    const int nh = ni >> 1, sel = ni & 1;
                    mma16816(acc[mi][ni], af[mi], bf[nh][sel], bf[nh][sel + 2]);
                }
            }
        }
    };

    // prologue: fill two stages (buffer 2 stays for kt=2's load in-loop)
    if (tid == 0) {
        load_stage(0, 0);
        load_stage(1, 1);
    }

    for (int kt = 0; kt < KTILES; kt++) {
        const int buf = kt % NSTAGE;
        // producer: refill lookahead-2 stage once all warps released it
        if (tid == 0 && kt + 2 < KTILES) {
            const int ld = kt + 2;
            if (ld >= NSTAGE)
                mbar_wait_parity(mbE[ld % NSTAGE], (uint32_t)(((ld - NSTAGE) / NSTAGE) & 1));
            load_stage(ld % NSTAGE, ld);
        }
        mbar_wait_parity(mbF[buf], (uint32_t)((kt / NSTAGE) & 1));
        compute_stage(buf);
        if (lane == 0)
            mbar_arrive(mbE[buf]);      // release stage; no CTA-wide barrier
    }

    // epilogue: diagonal-masked row-min, lane-quad reduce, global atomicMin
    // (register-only inputs: safe without any further synchronization)
    #pragma unroll
    for (int mi = 0; mi < 4; mi++) {
        #pragma unroll
        for (int half = 0; half < 2; half++) {
            const int gi = iBase + wm * 64 + mi * 16 + (lane >> 2) + half * 8;
            float vmin = CUDART_INF_F;
            #pragma unroll
            for (int ni = 0; ni < 4; ni++) {
                const int gj0 = jBase + wn * 32 + ni * 8 + 2 * (lane & 3);
                const float v0 = (gi == gj0)     ? CUDART_INF_F : acc[mi][ni][half * 2 + 0];
                const float v1 = (gi == gj0 + 1) ? CUDART_INF_F : acc[mi][ni][half * 2 + 1];
                vmin = fminf(vmin, fminf(v0, v1));
            }
            vmin = fminf(vmin, __shfl_xor_sync(0xffffffff, vmin, 1));
            vmin = fminf(vmin, __shfl_xor_sync(0xffffffff, vmin, 2));
            if ((lane & 3) == 0)
                atomicMin(&g_minenc[gi], enc_f32(vmin));
        }
    }
}

// ---------------------------------------------------------------------------
// Kernel 3: decode per-row min, compute mean relu(1 + diag - min)
// ---------------------------------------------------------------------------
__global__ __launch_bounds__(1024)
void final_loss_kernel(float* __restrict__ out) {
    const int t = threadIdx.x;   // 1024
    float sum = 0.f;
    for (int i = t; i < BDIM; i += 1024) {
        const float m = dec_f32(g_minenc[i]);
        const float l = 1.0f + g_diag[i] - m;
        sum += (l > 0.f) ? l : 0.f;
    }
    #pragma unroll
    for (int off = 16; off >= 1; off >>= 1)
        sum += __shfl_xor_sync(0xffffffff, sum, off);
    __shared__ float red[32];
    const int warp = t >> 5, lane = t & 31;
    if (lane == 0) red[warp] = sum;
    __syncthreads();
    if (warp == 0) {
        float v = red[lane];
        #pragma unroll
        for (int off = 16; off >= 1; off >>= 1)
            v += __shfl_xor_sync(0xffffffff, v, off);
        if (lane == 0) out[0] = v / (float)BDIM;
    }
}

// ---------------------------------------------------------------------------
// host-side tensormap encoding (runtime-resolved driver entry point; no -lcuda)
// ---------------------------------------------------------------------------
typedef CUresult (*EncodeTiledFn)(
    CUtensorMap*, CUtensorMapDataType, cuuint32_t, void*,
    const cuuint64_t*, const cuuint64_t*, const cuuint32_t*, const cuuint32_t*,
    CUtensorMapInterleave, CUtensorMapSwizzle, CUtensorMapL2promotion,
    CUtensorMapFloatOOBfill);

static void encode_map(EncodeTiledFn enc, CUtensorMap* tm, void* base) {
    cuuint64_t dims[2]    = { (cuuint64_t)DDIM, (cuuint64_t)BDIM };
    cuuint64_t strides[1] = { (cuuint64_t)DDIM * sizeof(__half) };
    cuuint32_t box[2]     = { (cuuint32_t)BKH, (cuuint32_t)BM };   // 128 B x 128 rows
    cuuint32_t estr[2]    = { 1, 1 };
    enc(tm, CU_TENSOR_MAP_DATA_TYPE_FLOAT16, 2, base,
        dims, strides, box, estr,
        CU_TENSOR_MAP_INTERLEAVE_NONE, CU_TENSOR_MAP_SWIZZLE_128B,
        CU_TENSOR_MAP_L2_PROMOTION_L2_128B, CU_TENSOR_MAP_FLOAT_OOB_FILL_NONE);
}

extern "C" void kernel_launch(void* const* d_in, const int* in_sizes, int n_in,
                              void* d_out, int out_size) {
    const float* anchor   = (const float*)d_in[0];
    const float* positive = (const float*)d_in[1];
    float* out = (float*)d_out;

    // resolve cuTensorMapEncodeTiled through cudart (host-only, graph-safe)
    EncodeTiledFn enc = nullptr;
    cudaDriverEntryPointQueryResult qres;
    cudaGetDriverEntryPoint("cuTensorMapEncodeTiled", (void**)&enc,
                            cudaEnableDefault, &qres);

    void *pa = nullptr, *pp = nullptr;
    cudaGetSymbolAddress(&pa, g_A);
    cudaGetSymbolAddress(&pp, g_P);

    CUtensorMap tmA, tmP;
    encode_map(enc, &tmA, pa);
    encode_map(enc, &tmP, pp);

    cudaFuncSetAttribute(gemm_min_mma, cudaFuncAttributeMaxDynamicSharedMemorySize, SMEMB);

    normalize_diag_kernel<<<BDIM / 4, 128>>>(anchor, positive);
    dim3 grid(BDIM / BN, BDIM / BM);
    gemm_min_mma<<<grid, 256, SMEMB>>>(tmA, tmP);
    final_loss_kernel<<<1, 1024>>>(out);
}